// round 15
// baseline (speedup 1.0000x reference)
#include <cuda_runtime.h>
#include <cuda_bf16.h>
#include <stdint.h>
#include <math.h>

#define B 2
#define S 2048
#define E 1024
#define H 16
#define D 64
#define MROWS (B*S)                   // 4096
#define KPAIRS 512                    // 1024 floats -> 512 bf16 pairs
#define OUT_ELEMS (B*S*E)             // 4194304
#define ATTN_ELEMS ((size_t)B*H*S*S)  // 134217728

// ------------------------- device scratch (no runtime alloc) -----------------
__device__ uint32_t g_xq_hi[MROWS*KPAIRS], g_xq_lo[MROWS*KPAIRS];
__device__ uint32_t g_xk_hi[MROWS*KPAIRS], g_xk_lo[MROWS*KPAIRS];
__device__ uint32_t g_xv_hi[MROWS*KPAIRS], g_xv_lo[MROWS*KPAIRS];
__device__ uint32_t g_wq_hi[E*KPAIRS],  g_wq_lo[E*KPAIRS];
__device__ uint32_t g_wk_hi[E*KPAIRS],  g_wk_lo[E*KPAIRS];
__device__ uint32_t g_wv_hi[E*KPAIRS],  g_wv_lo[E*KPAIRS];
__device__ uint32_t g_wo_hi[E*KPAIRS],  g_wo_lo[E*KPAIRS];
__device__ uint32_t g_qhi[B*H*S*(D/2)], g_qlo[B*H*S*(D/2)];   // packed (b,h,s,d/2)
__device__ uint32_t g_khi[B*H*S*(D/2)], g_klo[B*H*S*(D/2)];
__device__ uint32_t g_vthi[B*H*D*(S/2)], g_vtlo[B*H*D*(S/2)];  // V^T packed [bh][d][s/2]
__device__ uint32_t g_chi[MROWS*KPAIRS], g_clo[MROWS*KPAIRS];  // ctx packed (b,s,e/2)
__device__ float    g_l[B*H*S];                                // softmax denominators

// ------------------------------- helpers -------------------------------------
__device__ __forceinline__ void split_pack(float x0, float x1,
                                           uint32_t& hi, uint32_t& lo) {
    __nv_bfloat16 h0 = __float2bfloat16(x0);
    __nv_bfloat16 h1 = __float2bfloat16(x1);
    __nv_bfloat16 l0 = __float2bfloat16(x0 - __bfloat162float(h0));
    __nv_bfloat16 l1 = __float2bfloat16(x1 - __bfloat162float(h1));
    hi = ((uint32_t)__bfloat16_as_ushort(h1) << 16) | __bfloat16_as_ushort(h0);
    lo = ((uint32_t)__bfloat16_as_ushort(l1) << 16) | __bfloat16_as_ushort(l0);
}

__device__ __forceinline__ void mma_bf16(float* d, const uint32_t* a, const uint32_t* b) {
    asm volatile(
        "mma.sync.aligned.m16n8k16.row.col.f32.bf16.bf16.f32 "
        "{%0,%1,%2,%3},{%4,%5,%6,%7},{%8,%9},{%0,%1,%2,%3};\n"
        : "+f"(d[0]), "+f"(d[1]), "+f"(d[2]), "+f"(d[3])
        : "r"(a[0]), "r"(a[1]), "r"(a[2]), "r"(a[3]), "r"(b[0]), "r"(b[1]));
}

__device__ __forceinline__ void cp16(uint32_t saddr, const void* gptr) {
    asm volatile("cp.async.cg.shared.global [%0], [%1], 16;\n"
                 :: "r"(saddr), "l"(gptr));
}
#define CP_COMMIT() asm volatile("cp.async.commit_group;\n" ::: "memory")

// ------------------------- pack fp32 -> bf16 hi/lo pairs ---------------------
__global__ __launch_bounds__(256)
void pack3_kernel(const float* __restrict__ s0, const float* __restrict__ s1,
                  const float* __restrict__ s2,
                  uint32_t* __restrict__ h0, uint32_t* __restrict__ l0_,
                  uint32_t* __restrict__ h1, uint32_t* __restrict__ l1_,
                  uint32_t* __restrict__ h2, uint32_t* __restrict__ l2_,
                  int npairs)
{
    int i = blockIdx.x * 256 + threadIdx.x;
    if (i >= npairs) return;
    const float* src = (blockIdx.y == 0) ? s0 : (blockIdx.y == 1) ? s1 : s2;
    uint32_t* hi = (blockIdx.y == 0) ? h0 : (blockIdx.y == 1) ? h1 : h2;
    uint32_t* lo = (blockIdx.y == 0) ? l0_ : (blockIdx.y == 1) ? l1_ : l2_;
    float2 v = ((const float2*)src)[i];
    uint32_t h, l;
    split_pack(v.x, v.y, h, l);
    hi[i] = h; lo[i] = l;
}

__global__ __launch_bounds__(256)
void pack4_kernel(const float* __restrict__ s0, const float* __restrict__ s1,
                  const float* __restrict__ s2, const float* __restrict__ s3,
                  uint32_t* __restrict__ h0, uint32_t* __restrict__ l0_,
                  uint32_t* __restrict__ h1, uint32_t* __restrict__ l1_,
                  uint32_t* __restrict__ h2, uint32_t* __restrict__ l2_,
                  uint32_t* __restrict__ h3, uint32_t* __restrict__ l3_,
                  int npairs)
{
    int i = blockIdx.x * 256 + threadIdx.x;
    if (i >= npairs) return;
    const float* src = (blockIdx.y == 0) ? s0 : (blockIdx.y == 1) ? s1
                     : (blockIdx.y == 2) ? s2 : s3;
    uint32_t* hi = (blockIdx.y == 0) ? h0 : (blockIdx.y == 1) ? h1
                 : (blockIdx.y == 2) ? h2 : h3;
    uint32_t* lo = (blockIdx.y == 0) ? l0_ : (blockIdx.y == 1) ? l1_
                 : (blockIdx.y == 2) ? l2_ : l3_;
    float2 v = ((const float2*)src)[i];
    uint32_t h, l;
    split_pack(v.x, v.y, h, l);
    hi[i] = h; lo[i] = l;
}

// ------------------------------- GEMM core -----------------------------------
#define STRG 36   // 32 pairs + pad
#define AH_O 0
#define AL_O (128*STRG)
#define WH_O (256*STRG)
#define WL_O (256*STRG + 64*STRG)
#define STAGE_W (384*STRG)                 // words per stage = 13824
#define SMEM_G (2*STAGE_W*4)               // 110592 bytes

__device__ __forceinline__
void gemm_mainloop(int rowBase, int colBase,
                   const uint32_t* __restrict__ Ahi, const uint32_t* __restrict__ Alo,
                   const uint32_t* __restrict__ Whi, const uint32_t* __restrict__ Wlo,
                   uint32_t* sg, float acc[2][4][4])
{
    const uint32_t sbase = (uint32_t)__cvta_generic_to_shared(sg);
    const int t = threadIdx.x;

    auto issue = [&](int kt, int st) {
        const int kp0g = kt * 32;
        const uint32_t sb = sbase + (uint32_t)st * (STAGE_W * 4);
        #pragma unroll
        for (int r = 0; r < 4; r++) {
            int idx = t + r * 256;
            int row = idx >> 3, c4 = (idx & 7) << 2;
            cp16(sb + (AH_O + row*STRG + c4) * 4,
                 Ahi + (size_t)(rowBase + row) * KPAIRS + kp0g + c4);
            cp16(sb + (AL_O + row*STRG + c4) * 4,
                 Alo + (size_t)(rowBase + row) * KPAIRS + kp0g + c4);
        }
        #pragma unroll
        for (int r = 0; r < 2; r++) {
            int idx = t + r * 256;
            int row = idx >> 3, c4 = (idx & 7) << 2;
            cp16(sb + (WH_O + row*STRG + c4) * 4,
                 Whi + (size_t)(colBase + row) * KPAIRS + kp0g + c4);
            cp16(sb + (WL_O + row*STRG + c4) * 4,
                 Wlo + (size_t)(colBase + row) * KPAIRS + kp0g + c4);
        }
        CP_COMMIT();
    };

    const int lane = t & 31, g = lane >> 2, tg = lane & 3;
    const int warp = t >> 5, wm = warp >> 1, wn = warp & 1;

    issue(0, 0);
    issue(1, 1);

    for (int kt = 0; kt < 16; kt++) {
        if (kt < 15) asm volatile("cp.async.wait_group 1;\n" ::: "memory");
        else         asm volatile("cp.async.wait_group 0;\n" ::: "memory");
        __syncthreads();

        const uint32_t* Ah = sg + (kt & 1) * STAGE_W + AH_O;
        const uint32_t* Al = sg + (kt & 1) * STAGE_W + AL_O;
        const uint32_t* Wh = sg + (kt & 1) * STAGE_W + WH_O;
        const uint32_t* Wl = sg + (kt & 1) * STAGE_W + WL_O;

        #pragma unroll
        for (int ks = 0; ks < 4; ks++) {
            const int kp0 = ks * 8;
            uint32_t ah[2][4], al[2][4];
            #pragma unroll
            for (int mt = 0; mt < 2; mt++) {
                int r0 = (wm*32 + mt*16 + g) * STRG + kp0 + tg;
                int r8 = r0 + 8 * STRG;
                ah[mt][0] = Ah[r0]; ah[mt][1] = Ah[r8];
                ah[mt][2] = Ah[r0+4]; ah[mt][3] = Ah[r8+4];
                al[mt][0] = Al[r0]; al[mt][1] = Al[r8];
                al[mt][2] = Al[r0+4]; al[mt][3] = Al[r8+4];
            }
            #pragma unroll
            for (int nt = 0; nt < 4; nt++) {
                int nb = (wn*32 + nt*8 + g) * STRG + kp0 + tg;
                uint32_t bh[2] = { Wh[nb], Wh[nb+4] };
                uint32_t bl[2] = { Wl[nb], Wl[nb+4] };
                #pragma unroll
                for (int mt = 0; mt < 2; mt++) {
                    mma_bf16(acc[mt][nt], ah[mt], bh);
                    mma_bf16(acc[mt][nt], al[mt], bh);
                    mma_bf16(acc[mt][nt], ah[mt], bl);
                }
            }
        }
        __syncthreads();
        if (kt + 2 < 16) issue(kt + 2, kt & 1);
    }
}

// ---------------- merged Q/K/V projection: grid.z selects operand ------------
__global__ __launch_bounds__(256)
void qkv_gemm(const uint32_t* __restrict__ xqh, const uint32_t* __restrict__ xql,
              const uint32_t* __restrict__ xkh, const uint32_t* __restrict__ xkl,
              const uint32_t* __restrict__ xvh, const uint32_t* __restrict__ xvl,
              const uint32_t* __restrict__ wqh, const uint32_t* __restrict__ wql,
              const uint32_t* __restrict__ wkh, const uint32_t* __restrict__ wkl,
              const uint32_t* __restrict__ wvh, const uint32_t* __restrict__ wvl,
              const float* __restrict__ bq, const float* __restrict__ bk,
              const float* __restrict__ bv,
              uint32_t* __restrict__ qh, uint32_t* __restrict__ ql,
              uint32_t* __restrict__ kh, uint32_t* __restrict__ kl,
              uint32_t* __restrict__ vthi, uint32_t* __restrict__ vtlo)
{
    extern __shared__ uint32_t sg[];
    const int z = blockIdx.z;
    const uint32_t* Ahi = (z == 0) ? xqh : (z == 1) ? xkh : xvh;
    const uint32_t* Alo = (z == 0) ? xql : (z == 1) ? xkl : xvl;
    const uint32_t* Whi = (z == 0) ? wqh : (z == 1) ? wkh : wvh;
    const uint32_t* Wlo = (z == 0) ? wql : (z == 1) ? wkl : wvl;
    const float* bias   = (z == 0) ? bq  : (z == 1) ? bk  : bv;
    const float scale   = (z == 0) ? 0.125f : 1.0f;

    const int rowBase = blockIdx.y * 128, colBase = blockIdx.x * 64;
    float acc[2][4][4] = {};
    gemm_mainloop(rowBase, colBase, Ahi, Alo, Whi, Wlo, sg, acc);

    const int t = threadIdx.x, lane = t & 31, g = lane >> 2, tg = lane & 3;
    const int warp = t >> 5, wm = warp >> 1, wn = warp & 1;

    #pragma unroll
    for (int mt = 0; mt < 2; mt++) {
        #pragma unroll
        for (int nt = 0; nt < 4; nt++) {
            int m0 = rowBase + wm*32 + mt*16 + g;
            int n  = colBase + wn*32 + nt*8 + 2*tg;
            float b0 = bias[n], b1 = bias[n+1];
            float v00 = (acc[mt][nt][0] + b0) * scale;
            float v01 = (acc[mt][nt][1] + b1) * scale;
            float v10 = (acc[mt][nt][2] + b0) * scale;
            float v11 = (acc[mt][nt][3] + b1) * scale;
            if (z < 2) {
                uint32_t* oh = (z == 0) ? qh : kh;
                uint32_t* ol = (z == 0) ? ql : kl;
                int hh = n >> 6, dp = (n >> 1) & 31;
                {
                    int bb = m0 >> 11, ss = m0 & 2047;
                    size_t p = ((size_t)(bb*H + hh)*S + ss) * (D/2) + dp;
                    uint32_t hw, lw; split_pack(v00, v01, hw, lw);
                    oh[p] = hw; ol[p] = lw;
                }
                {
                    int m8 = m0 + 8, bb = m8 >> 11, ss = m8 & 2047;
                    size_t p = ((size_t)(bb*H + hh)*S + ss) * (D/2) + dp;
                    uint32_t hw, lw; split_pack(v10, v11, hw, lw);
                    oh[p] = hw; ol[p] = lw;
                }
            } else {
                float p00 = __shfl_down_sync(0xffffffffu, v00, 4);
                float p01 = __shfl_down_sync(0xffffffffu, v01, 4);
                float p10 = __shfl_down_sync(0xffffffffu, v10, 4);
                float p11 = __shfl_down_sync(0xffffffffu, v11, 4);
                if (!(g & 1)) {
                    int bb = m0 >> 11, ss = m0 & 2047;   // ss even
                    int hh = n >> 6, d0 = n & 63;
                    size_t base = ((size_t)(bb*H + hh) * D + d0) * (S/2) + (ss >> 1);
                    uint32_t hw, lw;
                    split_pack(v00, p00, hw, lw);
                    vthi[base] = hw;             vtlo[base] = lw;
                    split_pack(v01, p01, hw, lw);
                    vthi[base + (S/2)] = hw;     vtlo[base + (S/2)] = lw;
                    split_pack(v10, p10, hw, lw);
                    vthi[base + 4] = hw;         vtlo[base + 4] = lw;
                    split_pack(v11, p11, hw, lw);
                    vthi[base + (S/2) + 4] = hw; vtlo[base + (S/2) + 4] = lw;
                }
            }
        }
    }
}

// ---------------- out-projection GEMM (fp32 row-major out) -------------------
__global__ __launch_bounds__(256)
void gemm_out(const uint32_t* __restrict__ Ahi, const uint32_t* __restrict__ Alo,
              const uint32_t* __restrict__ Whi, const uint32_t* __restrict__ Wlo,
              const float* __restrict__ bias,
              float* __restrict__ outf)
{
    extern __shared__ uint32_t sg[];
    const int rowBase = blockIdx.y * 128, colBase = blockIdx.x * 64;
    float acc[2][4][4] = {};
    gemm_mainloop(rowBase, colBase, Ahi, Alo, Whi, Wlo, sg, acc);

    const int t = threadIdx.x, lane = t & 31, g = lane >> 2, tg = lane & 3;
    const int warp = t >> 5, wm = warp >> 1, wn = warp & 1;

    #pragma unroll
    for (int mt = 0; mt < 2; mt++) {
        #pragma unroll
        for (int nt = 0; nt < 4; nt++) {
            int m0 = rowBase + wm*32 + mt*16 + g;
            int n  = colBase + wn*32 + nt*8 + 2*tg;
            float b0 = bias[n], b1 = bias[n+1];
            *(float2*)(outf + (size_t)m0 * 1024 + n)
                = make_float2(acc[mt][nt][0] + b0, acc[mt][nt][1] + b1);
            *(float2*)(outf + (size_t)(m0 + 8) * 1024 + n)
                = make_float2(acc[mt][nt][2] + b0, acc[mt][nt][3] + b1);
        }
    }
}

// ------------------------------- attention -----------------------------------
// Register-resident P (FA2-style C->A fragment reuse). Max-free softmax, exp
// spilled straight from registers. Cross-warp cacc+l merge in the epilogue.
#define STRA 36
#define QH_W 0
#define QL_W 2304
#define KST_W 4608          // 2 stages of 4608 (Kh 2304 | Kl 2304)
#define VH_W 13824
#define VL_W 16128
#define XCH_W KST_W         // epilogue exchange (64x64 fp32) reuses K staging
#define LP_W (KST_W + 4096) // l partials [2][64]
#define SMEM_A3 (18432*4)   // 73728 bytes

__global__ __launch_bounds__(256)
void attn_tc(const uint32_t* __restrict__ qhi, const uint32_t* __restrict__ qlo,
             const uint32_t* __restrict__ khi, const uint32_t* __restrict__ klo,
             const uint32_t* __restrict__ vthi, const uint32_t* __restrict__ vtlo,
             float* __restrict__ attn_raw,
             float* __restrict__ gl,
             uint32_t* __restrict__ ctxhi, uint32_t* __restrict__ ctxlo,
             int write_attn)
{
    extern __shared__ uint32_t sa[];
    const uint32_t sab = (uint32_t)__cvta_generic_to_shared(sa);
    uint32_t* Qh = sa + QH_W;
    uint32_t* Ql = sa + QL_W;
    uint32_t* Vh = sa + VH_W;
    uint32_t* Vl = sa + VL_W;

    const int qt = blockIdx.x, h = blockIdx.y, b = blockIdx.z;
    const int bh = b * H + h;
    const int t = threadIdx.x, lane = t & 31, g = lane >> 2, tg = lane & 3;
    const int warp = t >> 5, wm = warp >> 1, wn = warp & 1;

    {
        const size_t qb = ((size_t)bh * S + qt * 64) * (D/2);
        #pragma unroll
        for (int r = 0; r < 2; r++) {
            int idx = t + r * 256;
            int row = idx >> 3, c4 = (idx & 7) << 2;
            *(uint4*)&Qh[row*STRA + c4] = *(const uint4*)(qhi + qb + row*(D/2) + c4);
            *(uint4*)&Ql[row*STRA + c4] = *(const uint4*)(qlo + qb + row*(D/2) + c4);
        }
    }

    {
        const size_t kb = ((size_t)bh * S) * (D/2);
        #pragma unroll
        for (int r = 0; r < 2; r++) {
            int idx = t + r * 256;
            int row = idx >> 3, c4 = (idx & 7) << 2;
            cp16(sab + (KST_W + row*STRA + c4)*4,        khi + kb + row*(D/2) + c4);
            cp16(sab + (KST_W + 2304 + row*STRA + c4)*4, klo + kb + row*(D/2) + c4);
        }
        CP_COMMIT();
    }

    float cacc[8][4] = {};
    float lsum_g = 0.0f, lsum_g8 = 0.0f;

    for (int kt = 0; kt < S/64; kt++) {
        __syncthreads();

        #pragma unroll
        for (int r = 0; r < 2; r++) {
            int idx = t + r * 256;
            int row = idx >> 3, c4 = (idx & 7) << 2;
            size_t vrow = ((size_t)bh * D + row) * (S/2) + kt*32;
            cp16(sab + (VH_W + row*STRA + c4)*4, vthi + vrow + c4);
            cp16(sab + (VL_W + row*STRA + c4)*4, vtlo + vrow + c4);
        }
        CP_COMMIT();
        if (kt + 1 < S/64) {
            const size_t kb = ((size_t)bh * S + (kt+1) * 64) * (D/2);
            const int st = (kt + 1) & 1;
            #pragma unroll
            for (int r = 0; r < 2; r++) {
                int idx = t + r * 256;
                int row = idx >> 3, c4 = (idx & 7) << 2;
                cp16(sab + (KST_W + st*4608 + row*STRA + c4)*4,        khi + kb + row*(D/2) + c4);
                cp16(sab + (KST_W + st*4608 + 2304 + row*STRA + c4)*4, klo + kb + row*(D/2) + c4);
            }
            CP_COMMIT();
        }

        if (kt + 1 < S/64) asm volatile("cp.async.wait_group 2;\n" ::: "memory");
        else               asm volatile("cp.async.wait_group 1;\n" ::: "memory");
        __syncthreads();

        const uint32_t* Khp = sa + KST_W + (kt & 1) * 4608;
        const uint32_t* Klp = Khp + 2304;

        float sacc[4][4] = {};
        #pragma unroll
        for (int ks = 0; ks < 4; ks++) {
            const int kp0 = ks * 8;
            uint32_t ah[4], al[4];
            int r0 = (wm*16 + g) * STRA + kp0 + tg;
            int r8 = r0 + 8 * STRA;
            ah[0] = Qh[r0]; ah[1] = Qh[r8]; ah[2] = Qh[r0+4]; ah[3] = Qh[r8+4];
            al[0] = Ql[r0]; al[1] = Ql[r8]; al[2] = Ql[r0+4]; al[3] = Ql[r8+4];
            #pragma unroll
            for (int nt = 0; nt < 4; nt++) {
                int nb = (wn*32 + nt*8 + g) * STRA + kp0 + tg;
                uint32_t bhf[2] = { Khp[nb], Khp[nb+4] };
                uint32_t blf[2] = { Klp[nb], Klp[nb+4] };
                mma_bf16(sacc[nt], ah, bhf);
                mma_bf16(sacc[nt], al, bhf);
                mma_bf16(sacc[nt], ah, blf);
            }
        }

        float e[4][4];
        #pragma unroll
        for (int nt = 0; nt < 4; nt++)
            #pragma unroll
            for (int i = 0; i < 4; i++)
                e[nt][i] = __expf(sacc[nt][i]);
        {
            float sg_ = 0.0f, s8_ = 0.0f;
            #pragma unroll
            for (int nt = 0; nt < 4; nt++) {
                sg_ += e[nt][0] + e[nt][1];
                s8_ += e[nt][2] + e[nt][3];
            }
            sg_ += __shfl_xor_sync(0xffffffffu, sg_, 1);
            sg_ += __shfl_xor_sync(0xffffffffu, sg_, 2);
            s8_ += __shfl_xor_sync(0xffffffffu, s8_, 1);
            s8_ += __shfl_xor_sync(0xffffffffu, s8_, 2);
            lsum_g  += sg_;
            lsum_g8 += s8_;
        }
        if (write_attn) {
            float* rb = attn_raw + (size_t)bh*S*S
                      + (size_t)(qt*64 + wm*16 + g) * S + kt*64 + wn*32;
            #pragma unroll
            for (int nt = 0; nt < 4; nt++) {
                *(float2*)(rb + nt*8 + 2*tg)       = make_float2(e[nt][0], e[nt][1]);
                *(float2*)(rb + 8*S + nt*8 + 2*tg) = make_float2(e[nt][2], e[nt][3]);
            }
        }
        uint32_t pah[2][4], pal[2][4];
        #pragma unroll
        for (int ks2 = 0; ks2 < 2; ks2++) {
            const int nA = 2*ks2, nB = 2*ks2 + 1;
            split_pack(e[nA][0], e[nA][1], pah[ks2][0], pal[ks2][0]);
            split_pack(e[nA][2], e[nA][3], pah[ks2][1], pal[ks2][1]);
            split_pack(e[nB][0], e[nB][1], pah[ks2][2], pal[ks2][2]);
            split_pack(e[nB][2], e[nB][3], pah[ks2][3], pal[ks2][3]);
        }

        if (kt + 1 < S/64) asm volatile("cp.async.wait_group 1;\n" ::: "memory");
        else               asm volatile("cp.async.wait_group 0;\n" ::: "memory");
        __syncthreads();

        #pragma unroll
        for (int ks2 = 0; ks2 < 2; ks2++) {
            const int kpb = wn*16 + ks2*8;
            #pragma unroll
            for (int nt = 0; nt < 8; nt++) {
                int nb = (nt*8 + g) * STRA + kpb + tg;
                uint32_t bhf[2] = { Vh[nb], Vh[nb+4] };
                uint32_t blf[2] = { Vl[nb], Vl[nb+4] };
                mma_bf16(cacc[nt], pah[ks2], bhf);
                mma_bf16(cacc[nt], pal[ks2], bhf);
                mma_bf16(cacc[nt], pah[ks2], blf);
            }
        }
    }

    __syncthreads();
    float* xch = (float*)(sa + XCH_W);
    float* lp  = (float*)(sa + LP_W);
    if (tg == 0) {
        lp[wn*64 + wm*16 + g]     = lsum_g;
        lp[wn*64 + wm*16 + g + 8] = lsum_g8;
    }
    if (wn == 1) {
        #pragma unroll
        for (int nt = 0; nt < 8; nt++) {
            int r0 = (wm*16 + g)*64 + nt*8 + 2*tg;
            int r8 = (wm*16 + g + 8)*64 + nt*8 + 2*tg;
            xch[r0]     = cacc[nt][0];
            xch[r0 + 1] = cacc[nt][1];
            xch[r8]     = cacc[nt][2];
            xch[r8 + 1] = cacc[nt][3];
        }
    }
    __syncthreads();
    if (wn == 0) {
        float l0 = lp[wm*16 + g]     + lp[64 + wm*16 + g];
        float l8 = lp[wm*16 + g + 8] + lp[64 + wm*16 + g + 8];
        float inv0 = 1.0f / l0, inv8 = 1.0f / l8;
        int s0 = qt*64 + wm*16 + g;
        #pragma unroll
        for (int nt = 0; nt < 8; nt++) {
            int r0 = (wm*16 + g)*64 + nt*8 + 2*tg;
            int r8 = (wm*16 + g + 8)*64 + nt*8 + 2*tg;
            float v0 = (cacc[nt][0] + xch[r0])     * inv0;
            float v1 = (cacc[nt][1] + xch[r0 + 1]) * inv0;
            float v2 = (cacc[nt][2] + xch[r8])     * inv8;
            float v3 = (cacc[nt][3] + xch[r8 + 1]) * inv8;
            int pp = h*32 + nt*4 + tg;
            uint32_t hw, lw;
            split_pack(v0, v1, hw, lw);
            size_t p0 = ((size_t)b*S + s0) * KPAIRS + pp;
            ctxhi[p0] = hw; ctxlo[p0] = lw;
            split_pack(v2, v3, hw, lw);
            size_t p8 = ((size_t)b*S + s0 + 8) * KPAIRS + pp;
            ctxhi[p8] = hw; ctxlo[p8] = lw;
        }
    }
    if (write_attn && t < 64)
        gl[(size_t)bh*S + qt*64 + t] = lp[t] + lp[64 + t];
}

// -------------- normalize spilled exp-scores: pure 1/l scale -----------------
__global__ __launch_bounds__(256)
void norm_kernel(float* __restrict__ attn)
{
    const size_t i4 = (size_t)blockIdx.x * blockDim.x + threadIdx.x;
    if (i4 >= ATTN_ELEMS / 4) return;
    const size_t row = i4 >> 9;
    const float invl = 1.0f / g_l[row];
    float4 v = ((const float4*)attn)[i4];
    v.x *= invl;
    v.y *= invl;
    v.z *= invl;
    v.w *= invl;
    ((float4*)attn)[i4] = v;
}

// --------------------------------- launch ------------------------------------
extern "C" void kernel_launch(void* const* d_in, const int* in_sizes, int n_in,
                              void* d_out, int out_size)
{
    const float* query = (const float*)d_in[0];
    const float* key   = (const float*)d_in[1];
    const float* value = (const float*)d_in[2];
    const float* Wq = (const float*)d_in[3];
    const float* bq = (const float*)d_in[4];
    const float* Wk = (const float*)d_in[5];
    const float* bk = (const float*)d_in[6];
    const float* Wv = (const float*)d_in[7];
    const float* bv = (const float*)d_in[8];
    const float* Wo = (const float*)d_in[9];
    const float* bo = (const float*)d_in[10];

    float* out_ptr = (float*)d_out;
    const int write_attn = (out_size >= (int)(OUT_ELEMS + ATTN_ELEMS)) ? 1 : 0;
    float* attn_ptr = out_ptr + OUT_ELEMS;

    void* xqh; cudaGetSymbolAddress(&xqh, g_xq_hi);
    void* xql; cudaGetSymbolAddress(&xql, g_xq_lo);
    void* xkh; cudaGetSymbolAddress(&xkh, g_xk_hi);
    void* xkl; cudaGetSymbolAddress(&xkl, g_xk_lo);
    void* xvh; cudaGetSymbolAddress(&xvh, g_xv_hi);
    void* xvl; cudaGetSymbolAddress(&xvl, g_xv_lo);
    void* wqh; cudaGetSymbolAddress(&wqh, g_wq_hi);
    void* wql; cudaGetSymbolAddress(&wql, g_wq_lo);
    void* wkh; cudaGetSymbolAddress(&wkh, g_wk_hi);
    void* wkl; cudaGetSymbolAddress(&wkl, g_wk_lo);
    void* wvh; cudaGetSymbolAddress(&wvh, g_wv_hi);
    void* wvl; cudaGetSymbolAddress(&wvl, g_wv_lo);
    void* woh; cudaGetSymbolAddress(&woh, g_wo_hi);
    void* wol; cudaGetSymbolAddress(&wol, g_wo_lo);
    void* qh;  cudaGetSymbolAddress(&qh,  g_qhi);
    void* ql;  cudaGetSymbolAddress(&ql,  g_qlo);
    void* kh;  cudaGetSymbolAddress(&kh,  g_khi);
    void* kl;  cudaGetSymbolAddress(&kl,  g_klo);
    void* vth; cudaGetSymbolAddress(&vth, g_vthi);
    void* vtl; cudaGetSymbolAddress(&vtl, g_vtlo);
    void* ch;  cudaGetSymbolAddress(&ch,  g_chi);
    void* cl;  cudaGetSymbolAddress(&cl,  g_clo);
    void* ll;  cudaGetSymbolAddress(&ll,  g_l);

    const int npi = MROWS * KPAIRS;   // 2,097,152
    const int npw = E * KPAIRS;       // 524,288

    pack3_kernel<<<dim3(npi/256, 3), 256>>>(
        query, key, value,
        (uint32_t*)xqh, (uint32_t*)xql,
        (uint32_t*)xkh, (uint32_t*)xkl,
        (uint32_t*)xvh, (uint32_t*)xvl, npi);
    pack4_kernel<<<dim3(npw/256, 4), 256>>>(
        Wq, Wk, Wv, Wo,
        (uint32_t*)wqh, (uint32_t*)wql,
        (uint32_t*)wkh, (uint32_t*)wkl,
        (uint32_t*)wvh, (uint32_t*)wvl,
        (uint32_t*)woh, (uint32_t*)wol, npw);

    cudaFuncSetAttribute(qkv_gemm, cudaFuncAttributeMaxDynamicSharedMemorySize, SMEM_G);
    cudaFuncSetAttribute(gemm_out, cudaFuncAttributeMaxDynamicSharedMemorySize, SMEM_G);
    cudaFuncSetAttribute(attn_tc,  cudaFuncAttributeMaxDynamicSharedMemorySize, SMEM_A3);

    dim3 gblk(256);

    qkv_gemm<<<dim3(16, 32, 3), gblk, SMEM_G>>>(
        (const uint32_t*)xqh, (const uint32_t*)xql,
        (const uint32_t*)xkh, (const uint32_t*)xkl,
        (const uint32_t*)xvh, (const uint32_t*)xvl,
        (const uint32_t*)wqh, (const uint32_t*)wql,
        (const uint32_t*)wkh, (const uint32_t*)wkl,
        (const uint32_t*)wvh, (const uint32_t*)wvl,
        bq, bk, bv,
        (uint32_t*)qh, (uint32_t*)ql,
        (uint32_t*)kh, (uint32_t*)kl,
        (uint32_t*)vth, (uint32_t*)vtl);

    dim3 agrid(S/64, H, B);
    attn_tc<<<agrid, gblk, SMEM_A3>>>((const uint32_t*)qh, (const uint32_t*)ql,
                                      (const uint32_t*)kh, (const uint32_t*)kl,
                                      (const uint32_t*)vth, (const uint32_t*)vtl,
                                      attn_ptr, (float*)ll,
                                      (uint32_t*)ch, (uint32_t*)cl, write_attn);

    if (write_attn) {
        // graph fork: norm (DRAM-bound) runs parallel to gemm_out (tensor-bound)
        cudaStream_t s2 = 0;
        cudaEvent_t e1 = 0, e2 = 0;
        bool forked =
            (cudaStreamCreateWithFlags(&s2, cudaStreamNonBlocking) == cudaSuccess) &&
            (cudaEventCreateWithFlags(&e1, cudaEventDisableTiming) == cudaSuccess) &&
            (cudaEventCreateWithFlags(&e2, cudaEventDisableTiming) == cudaSuccess);
        const size_t n4 = ATTN_ELEMS / 4;
        if (forked) {
            cudaEventRecord(e1, 0);                 // after attn on main stream
            cudaStreamWaitEvent(s2, e1, 0);
            norm_kernel<<<(unsigned)((n4 + 255) / 256), 256, 0, s2>>>(attn_ptr);
            cudaEventRecord(e2, s2);
            gemm_out<<<dim3(16, 32), gblk, SMEM_G>>>(
                (const uint32_t*)ch, (const uint32_t*)cl,
                (const uint32_t*)woh, (const uint32_t*)wol,
                bo, out_ptr);
            cudaStreamWaitEvent(0, e2, 0);          // join before returning
            // release only when not capturing (graph still references them)
            cudaStreamCaptureStatus st = cudaStreamCaptureStatusNone;
            cudaStreamIsCapturing(0, &st);
            if (st == cudaStreamCaptureStatusNone) {
                cudaStreamDestroy(s2);
                cudaEventDestroy(e1);
                cudaEventDestroy(e2);
            }
        } else {
            norm_kernel<<<(unsigned)((n4 + 255) / 256), 256>>>(attn_ptr);
            gemm_out<<<dim3(16, 32), gblk, SMEM_G>>>(
                (const uint32_t*)ch, (const uint32_t*)cl,
                (const uint32_t*)woh, (const uint32_t*)wol,
                bo, out_ptr);
        }
    } else {
        gemm_out<<<dim3(16, 32), gblk, SMEM_G>>>(
            (const uint32_t*)ch, (const uint32_t*)cl,
            (const uint32_t*)woh, (const uint32_t*)wol,
            bo, out_ptr);
    }
}

// round 16
// speedup vs baseline: 1.1839x; 1.1839x over previous
#include <cuda_runtime.h>
#include <cuda_bf16.h>
#include <cuda_fp16.h>
#include <stdint.h>
#include <math.h>

#define B 2
#define S 2048
#define E 1024
#define H 16
#define D 64
#define MROWS (B*S)                   // 4096
#define KPAIRS 512                    // 1024 floats -> 512 pairs
#define OUT_ELEMS (B*S*E)             // 4194304
#define ATTN_ELEMS ((size_t)B*H*S*S)  // 134217728

// ------------------------- device scratch (no runtime alloc) -----------------
__device__ uint32_t g_xq_hi[MROWS*KPAIRS], g_xq_lo[MROWS*KPAIRS];   // fp16 limbs
__device__ uint32_t g_xk_hi[MROWS*KPAIRS], g_xk_lo[MROWS*KPAIRS];
__device__ uint32_t g_xv_hi[MROWS*KPAIRS], g_xv_lo[MROWS*KPAIRS];
__device__ uint32_t g_wq_h[E*KPAIRS], g_wk_h[E*KPAIRS];             // fp16 single
__device__ uint32_t g_wv_h[E*KPAIRS], g_wo_h[E*KPAIRS];
__device__ uint32_t g_qhi[B*H*S*(D/2)], g_qlo[B*H*S*(D/2)];         // bf16 limbs
__device__ uint32_t g_khi[B*H*S*(D/2)], g_klo[B*H*S*(D/2)];
__device__ uint32_t g_vth[B*H*D*(S/2)];                             // V^T fp16 single
__device__ uint32_t g_chi[MROWS*KPAIRS], g_clo[MROWS*KPAIRS];       // ctx fp16 limbs
__device__ float    g_l[B*H*S];

// ------------------------------- helpers -------------------------------------
__device__ __forceinline__ void split_pack(float x0, float x1,     // bf16 limbs
                                           uint32_t& hi, uint32_t& lo) {
    __nv_bfloat16 h0 = __float2bfloat16(x0);
    __nv_bfloat16 h1 = __float2bfloat16(x1);
    __nv_bfloat16 l0 = __float2bfloat16(x0 - __bfloat162float(h0));
    __nv_bfloat16 l1 = __float2bfloat16(x1 - __bfloat162float(h1));
    hi = ((uint32_t)__bfloat16_as_ushort(h1) << 16) | __bfloat16_as_ushort(h0);
    lo = ((uint32_t)__bfloat16_as_ushort(l1) << 16) | __bfloat16_as_ushort(l0);
}

__device__ __forceinline__ void split_pack_h(float x0, float x1,   // fp16 limbs
                                             uint32_t& hi, uint32_t& lo) {
    __half h0 = __float2half(x0);
    __half h1 = __float2half(x1);
    __half l0 = __float2half(x0 - __half2float(h0));
    __half l1 = __float2half(x1 - __half2float(h1));
    hi = ((uint32_t)__half_as_ushort(h1) << 16) | __half_as_ushort(h0);
    lo = ((uint32_t)__half_as_ushort(l1) << 16) | __half_as_ushort(l0);
}

__device__ __forceinline__ uint32_t pack_h2(float x0, float x1) {  // fp16 pair
    return ((uint32_t)__half_as_ushort(__float2half(x1)) << 16)
         | __half_as_ushort(__float2half(x0));
}

__device__ __forceinline__ void mma_bf16(float* d, const uint32_t* a, const uint32_t* b) {
    asm volatile(
        "mma.sync.aligned.m16n8k16.row.col.f32.bf16.bf16.f32 "
        "{%0,%1,%2,%3},{%4,%5,%6,%7},{%8,%9},{%0,%1,%2,%3};\n"
        : "+f"(d[0]), "+f"(d[1]), "+f"(d[2]), "+f"(d[3])
        : "r"(a[0]), "r"(a[1]), "r"(a[2]), "r"(a[3]), "r"(b[0]), "r"(b[1]));
}

__device__ __forceinline__ void mma_f16(float* d, const uint32_t* a, const uint32_t* b) {
    asm volatile(
        "mma.sync.aligned.m16n8k16.row.col.f32.f16.f16.f32 "
        "{%0,%1,%2,%3},{%4,%5,%6,%7},{%8,%9},{%0,%1,%2,%3};\n"
        : "+f"(d[0]), "+f"(d[1]), "+f"(d[2]), "+f"(d[3])
        : "r"(a[0]), "r"(a[1]), "r"(a[2]), "r"(a[3]), "r"(b[0]), "r"(b[1]));
}

__device__ __forceinline__ void cp16(uint32_t saddr, const void* gptr) {
    asm volatile("cp.async.cg.shared.global [%0], [%1], 16;\n"
                 :: "r"(saddr), "l"(gptr));
}
#define CP_COMMIT() asm volatile("cp.async.commit_group;\n" ::: "memory")

// ------------------- pack fp32 inputs -> fp16 hi/lo pairs --------------------
__global__ __launch_bounds__(256)
void pack3_kernel(const float* __restrict__ s0, const float* __restrict__ s1,
                  const float* __restrict__ s2,
                  uint32_t* __restrict__ h0, uint32_t* __restrict__ l0_,
                  uint32_t* __restrict__ h1, uint32_t* __restrict__ l1_,
                  uint32_t* __restrict__ h2, uint32_t* __restrict__ l2_,
                  int npairs)
{
    int i = blockIdx.x * 256 + threadIdx.x;
    if (i >= npairs) return;
    const float* src = (blockIdx.y == 0) ? s0 : (blockIdx.y == 1) ? s1 : s2;
    uint32_t* hi = (blockIdx.y == 0) ? h0 : (blockIdx.y == 1) ? h1 : h2;
    uint32_t* lo = (blockIdx.y == 0) ? l0_ : (blockIdx.y == 1) ? l1_ : l2_;
    float2 v = ((const float2*)src)[i];
    uint32_t h, l;
    split_pack_h(v.x, v.y, h, l);
    hi[i] = h; lo[i] = l;
}

// ------------------- pack fp32 weights -> single fp16 pairs ------------------
__global__ __launch_bounds__(256)
void pack4h_kernel(const float* __restrict__ s0, const float* __restrict__ s1,
                   const float* __restrict__ s2, const float* __restrict__ s3,
                   uint32_t* __restrict__ h0, uint32_t* __restrict__ h1,
                   uint32_t* __restrict__ h2, uint32_t* __restrict__ h3,
                   int npairs)
{
    int i = blockIdx.x * 256 + threadIdx.x;
    if (i >= npairs) return;
    const float* src = (blockIdx.y == 0) ? s0 : (blockIdx.y == 1) ? s1
                     : (blockIdx.y == 2) ? s2 : s3;
    uint32_t* hi = (blockIdx.y == 0) ? h0 : (blockIdx.y == 1) ? h1
                 : (blockIdx.y == 2) ? h2 : h3;
    float2 v = ((const float2*)src)[i];
    hi[i] = pack_h2(v.x, v.y);
}

// --------------------- GEMM core: one-sided 2-term fp16 ----------------------
// C[m][n] = dot(A[m,:], W[n,:]): A = exact 2-limb fp16, W = single fp16.
#define STRG 36   // 32 pairs + pad
#define A2H_O 0
#define A2L_O (128*STRG)
#define W2H_O (256*STRG)
#define STAGE2_W (320*STRG)                // 11520 words/stage
#define SMEM_G2 (2*STAGE2_W*4)             // 92160 bytes

__device__ __forceinline__
void gemm_mainloop2(int rowBase, int colBase,
                    const uint32_t* __restrict__ Ahi, const uint32_t* __restrict__ Alo,
                    const uint32_t* __restrict__ Wh_,
                    uint32_t* sg, float acc[2][4][4])
{
    const uint32_t sbase = (uint32_t)__cvta_generic_to_shared(sg);
    const int t = threadIdx.x;

    auto issue = [&](int kt, int st) {
        const int kp0g = kt * 32;
        const uint32_t sb = sbase + (uint32_t)st * (STAGE2_W * 4);
        #pragma unroll
        for (int r = 0; r < 4; r++) {
            int idx = t + r * 256;
            int row = idx >> 3, c4 = (idx & 7) << 2;
            cp16(sb + (A2H_O + row*STRG + c4) * 4,
                 Ahi + (size_t)(rowBase + row) * KPAIRS + kp0g + c4);
            cp16(sb + (A2L_O + row*STRG + c4) * 4,
                 Alo + (size_t)(rowBase + row) * KPAIRS + kp0g + c4);
        }
        #pragma unroll
        for (int r = 0; r < 2; r++) {
            int idx = t + r * 256;
            int row = idx >> 3, c4 = (idx & 7) << 2;
            cp16(sb + (W2H_O + row*STRG + c4) * 4,
                 Wh_ + (size_t)(colBase + row) * KPAIRS + kp0g + c4);
        }
        CP_COMMIT();
    };

    const int lane = t & 31, g = lane >> 2, tg = lane & 3;
    const int warp = t >> 5, wm = warp >> 1, wn = warp & 1;

    issue(0, 0);
    issue(1, 1);

    for (int kt = 0; kt < 16; kt++) {
        if (kt < 15) asm volatile("cp.async.wait_group 1;\n" ::: "memory");
        else         asm volatile("cp.async.wait_group 0;\n" ::: "memory");
        __syncthreads();

        const uint32_t* Ah = sg + (kt & 1) * STAGE2_W + A2H_O;
        const uint32_t* Al = sg + (kt & 1) * STAGE2_W + A2L_O;
        const uint32_t* Wh = sg + (kt & 1) * STAGE2_W + W2H_O;

        #pragma unroll
        for (int ks = 0; ks < 4; ks++) {
            const int kp0 = ks * 8;
            uint32_t ah[2][4], al[2][4];
            #pragma unroll
            for (int mt = 0; mt < 2; mt++) {
                int r0 = (wm*32 + mt*16 + g) * STRG + kp0 + tg;
                int r8 = r0 + 8 * STRG;
                ah[mt][0] = Ah[r0]; ah[mt][1] = Ah[r8];
                ah[mt][2] = Ah[r0+4]; ah[mt][3] = Ah[r8+4];
                al[mt][0] = Al[r0]; al[mt][1] = Al[r8];
                al[mt][2] = Al[r0+4]; al[mt][3] = Al[r8+4];
            }
            #pragma unroll
            for (int nt = 0; nt < 4; nt++) {
                int nb = (wn*32 + nt*8 + g) * STRG + kp0 + tg;
                uint32_t bh[2] = { Wh[nb], Wh[nb+4] };
                #pragma unroll
                for (int mt = 0; mt < 2; mt++) {
                    mma_f16(acc[mt][nt], ah[mt], bh);
                    mma_f16(acc[mt][nt], al[mt], bh);
                }
            }
        }
        __syncthreads();
        if (kt + 2 < 16) issue(kt + 2, kt & 1);
    }
}

// ---------------- merged Q/K/V projection: grid.z selects operand ------------
__global__ __launch_bounds__(256)
void qkv_gemm(const uint32_t* __restrict__ xqh, const uint32_t* __restrict__ xql,
              const uint32_t* __restrict__ xkh, const uint32_t* __restrict__ xkl,
              const uint32_t* __restrict__ xvh, const uint32_t* __restrict__ xvl,
              const uint32_t* __restrict__ wqh, const uint32_t* __restrict__ wkh,
              const uint32_t* __restrict__ wvh,
              const float* __restrict__ bq, const float* __restrict__ bk,
              const float* __restrict__ bv,
              uint32_t* __restrict__ qh, uint32_t* __restrict__ ql,
              uint32_t* __restrict__ kh, uint32_t* __restrict__ kl,
              uint32_t* __restrict__ vth)
{
    extern __shared__ uint32_t sg[];
    const int z = blockIdx.z;
    const uint32_t* Ahi = (z == 0) ? xqh : (z == 1) ? xkh : xvh;
    const uint32_t* Alo = (z == 0) ? xql : (z == 1) ? xkl : xvl;
    const uint32_t* Wh_ = (z == 0) ? wqh : (z == 1) ? wkh : wvh;
    const float* bias   = (z == 0) ? bq  : (z == 1) ? bk  : bv;
    const float scale   = (z == 0) ? 0.125f : 1.0f;

    const int rowBase = blockIdx.y * 128, colBase = blockIdx.x * 64;
    float acc[2][4][4] = {};
    gemm_mainloop2(rowBase, colBase, Ahi, Alo, Wh_, sg, acc);

    const int t = threadIdx.x, lane = t & 31, g = lane >> 2, tg = lane & 3;
    const int warp = t >> 5, wm = warp >> 1, wn = warp & 1;

    #pragma unroll
    for (int mt = 0; mt < 2; mt++) {
        #pragma unroll
        for (int nt = 0; nt < 4; nt++) {
            int m0 = rowBase + wm*32 + mt*16 + g;
            int n  = colBase + wn*32 + nt*8 + 2*tg;
            float b0 = bias[n], b1 = bias[n+1];
            float v00 = (acc[mt][nt][0] + b0) * scale;
            float v01 = (acc[mt][nt][1] + b1) * scale;
            float v10 = (acc[mt][nt][2] + b0) * scale;
            float v11 = (acc[mt][nt][3] + b1) * scale;
            if (z < 2) {
                uint32_t* oh = (z == 0) ? qh : kh;
                uint32_t* ol = (z == 0) ? ql : kl;
                int hh = n >> 6, dp = (n >> 1) & 31;
                {
                    int bb = m0 >> 11, ss = m0 & 2047;
                    size_t p = ((size_t)(bb*H + hh)*S + ss) * (D/2) + dp;
                    uint32_t hw, lw; split_pack(v00, v01, hw, lw);
                    oh[p] = hw; ol[p] = lw;
                }
                {
                    int m8 = m0 + 8, bb = m8 >> 11, ss = m8 & 2047;
                    size_t p = ((size_t)(bb*H + hh)*S + ss) * (D/2) + dp;
                    uint32_t hw, lw; split_pack(v10, v11, hw, lw);
                    oh[p] = hw; ol[p] = lw;
                }
            } else {
                // V^T direct, single fp16 limb
                float p00 = __shfl_down_sync(0xffffffffu, v00, 4);
                float p01 = __shfl_down_sync(0xffffffffu, v01, 4);
                float p10 = __shfl_down_sync(0xffffffffu, v10, 4);
                float p11 = __shfl_down_sync(0xffffffffu, v11, 4);
                if (!(g & 1)) {
                    int bb = m0 >> 11, ss = m0 & 2047;   // ss even
                    int hh = n >> 6, d0 = n & 63;
                    size_t base = ((size_t)(bb*H + hh) * D + d0) * (S/2) + (ss >> 1);
                    vth[base]             = pack_h2(v00, p00);
                    vth[base + (S/2)]     = pack_h2(v01, p01);
                    vth[base + 4]         = pack_h2(v10, p10);
                    vth[base + (S/2) + 4] = pack_h2(v11, p11);
                }
            }
        }
    }
}

// ---------------- out-projection GEMM (ctx fp16 limbs x Wo_h) ----------------
__global__ __launch_bounds__(256)
void gemm_out(const uint32_t* __restrict__ Ahi, const uint32_t* __restrict__ Alo,
              const uint32_t* __restrict__ Wh_,
              const float* __restrict__ bias,
              float* __restrict__ outf)
{
    extern __shared__ uint32_t sg[];
    const int rowBase = blockIdx.y * 128, colBase = blockIdx.x * 64;
    float acc[2][4][4] = {};
    gemm_mainloop2(rowBase, colBase, Ahi, Alo, Wh_, sg, acc);

    const int t = threadIdx.x, lane = t & 31, g = lane >> 2, tg = lane & 3;
    const int warp = t >> 5, wm = warp >> 1, wn = warp & 1;

    #pragma unroll
    for (int mt = 0; mt < 2; mt++) {
        #pragma unroll
        for (int nt = 0; nt < 4; nt++) {
            int m0 = rowBase + wm*32 + mt*16 + g;
            int n  = colBase + wn*32 + nt*8 + 2*tg;
            float b0 = bias[n], b1 = bias[n+1];
            *(float2*)(outf + (size_t)m0 * 1024 + n)
                = make_float2(acc[mt][nt][0] + b0, acc[mt][nt][1] + b1);
            *(float2*)(outf + (size_t)(m0 + 8) * 1024 + n)
                = make_float2(acc[mt][nt][2] + b0, acc[mt][nt][3] + b1);
        }
    }
}

// ------------------------------- attention -----------------------------------
// QK: 3-term bf16 (score-critical). PV: one-sided 2-term fp16 (P 2-limb x Vh).
// Register-resident P; max-free softmax; exp spilled from registers.
#define STRA 36
#define QH_W 0
#define QL_W 2304
#define KST_W 4608          // 2 stages of 4608 (Kh 2304 | Kl 2304)
#define VH_W 13824          // 2304 words (fp16 single limb)
#define XCH_W KST_W         // epilogue exchange (64x64 fp32) reuses K staging
#define LP_W (KST_W + 4096) // l partials [2][64]
#define SMEM_A4 (16128*4)   // 64512 bytes

__global__ __launch_bounds__(256)
void attn_tc(const uint32_t* __restrict__ qhi, const uint32_t* __restrict__ qlo,
             const uint32_t* __restrict__ khi, const uint32_t* __restrict__ klo,
             const uint32_t* __restrict__ vth,
             float* __restrict__ attn_raw,
             float* __restrict__ gl,
             uint32_t* __restrict__ ctxhi, uint32_t* __restrict__ ctxlo,
             int write_attn)
{
    extern __shared__ uint32_t sa[];
    const uint32_t sab = (uint32_t)__cvta_generic_to_shared(sa);
    uint32_t* Qh = sa + QH_W;
    uint32_t* Ql = sa + QL_W;
    uint32_t* Vh = sa + VH_W;

    const int qt = blockIdx.x, h = blockIdx.y, b = blockIdx.z;
    const int bh = b * H + h;
    const int t = threadIdx.x, lane = t & 31, g = lane >> 2, tg = lane & 3;
    const int warp = t >> 5, wm = warp >> 1, wn = warp & 1;

    {
        const size_t qb = ((size_t)bh * S + qt * 64) * (D/2);
        #pragma unroll
        for (int r = 0; r < 2; r++) {
            int idx = t + r * 256;
            int row = idx >> 3, c4 = (idx & 7) << 2;
            *(uint4*)&Qh[row*STRA + c4] = *(const uint4*)(qhi + qb + row*(D/2) + c4);
            *(uint4*)&Ql[row*STRA + c4] = *(const uint4*)(qlo + qb + row*(D/2) + c4);
        }
    }

    {
        const size_t kb = ((size_t)bh * S) * (D/2);
        #pragma unroll
        for (int r = 0; r < 2; r++) {
            int idx = t + r * 256;
            int row = idx >> 3, c4 = (idx & 7) << 2;
            cp16(sab + (KST_W + row*STRA + c4)*4,        khi + kb + row*(D/2) + c4);
            cp16(sab + (KST_W + 2304 + row*STRA + c4)*4, klo + kb + row*(D/2) + c4);
        }
        CP_COMMIT();
    }

    float cacc[8][4] = {};
    float lsum_g = 0.0f, lsum_g8 = 0.0f;

    for (int kt = 0; kt < S/64; kt++) {
        __syncthreads();

        // issue V(kt): single fp16 limb, 512 16B chunks
        #pragma unroll
        for (int r = 0; r < 2; r++) {
            int idx = t + r * 256;
            int row = idx >> 3, c4 = (idx & 7) << 2;
            size_t vrow = ((size_t)bh * D + row) * (S/2) + kt*32;
            cp16(sab + (VH_W + row*STRA + c4)*4, vth + vrow + c4);
        }
        CP_COMMIT();
        if (kt + 1 < S/64) {
            const size_t kb = ((size_t)bh * S + (kt+1) * 64) * (D/2);
            const int st = (kt + 1) & 1;
            #pragma unroll
            for (int r = 0; r < 2; r++) {
                int idx = t + r * 256;
                int row = idx >> 3, c4 = (idx & 7) << 2;
                cp16(sab + (KST_W + st*4608 + row*STRA + c4)*4,        khi + kb + row*(D/2) + c4);
                cp16(sab + (KST_W + st*4608 + 2304 + row*STRA + c4)*4, klo + kb + row*(D/2) + c4);
            }
            CP_COMMIT();
        }

        if (kt + 1 < S/64) asm volatile("cp.async.wait_group 2;\n" ::: "memory");
        else               asm volatile("cp.async.wait_group 1;\n" ::: "memory");
        __syncthreads();

        const uint32_t* Khp = sa + KST_W + (kt & 1) * 4608;
        const uint32_t* Klp = Khp + 2304;

        // S = Q @ K^T : 3-term bf16
        float sacc[4][4] = {};
        #pragma unroll
        for (int ks = 0; ks < 4; ks++) {
            const int kp0 = ks * 8;
            uint32_t ah[4], al[4];
            int r0 = (wm*16 + g) * STRA + kp0 + tg;
            int r8 = r0 + 8 * STRA;
            ah[0] = Qh[r0]; ah[1] = Qh[r8]; ah[2] = Qh[r0+4]; ah[3] = Qh[r8+4];
            al[0] = Ql[r0]; al[1] = Ql[r8]; al[2] = Ql[r0+4]; al[3] = Ql[r8+4];
            #pragma unroll
            for (int nt = 0; nt < 4; nt++) {
                int nb = (wn*32 + nt*8 + g) * STRA + kp0 + tg;
                uint32_t bhf[2] = { Khp[nb], Khp[nb+4] };
                uint32_t blf[2] = { Klp[nb], Klp[nb+4] };
                mma_bf16(sacc[nt], ah, bhf);
                mma_bf16(sacc[nt], al, bhf);
                mma_bf16(sacc[nt], ah, blf);
            }
        }

        float e[4][4];
        #pragma unroll
        for (int nt = 0; nt < 4; nt++)
            #pragma unroll
            for (int i = 0; i < 4; i++)
                e[nt][i] = __expf(sacc[nt][i]);
        {
            float sg_ = 0.0f, s8_ = 0.0f;
            #pragma unroll
            for (int nt = 0; nt < 4; nt++) {
                sg_ += e[nt][0] + e[nt][1];
                s8_ += e[nt][2] + e[nt][3];
            }
            sg_ += __shfl_xor_sync(0xffffffffu, sg_, 1);
            sg_ += __shfl_xor_sync(0xffffffffu, sg_, 2);
            s8_ += __shfl_xor_sync(0xffffffffu, s8_, 1);
            s8_ += __shfl_xor_sync(0xffffffffu, s8_, 2);
            lsum_g  += sg_;
            lsum_g8 += s8_;
        }
        if (write_attn) {
            float* rb = attn_raw + (size_t)bh*S*S
                      + (size_t)(qt*64 + wm*16 + g) * S + kt*64 + wn*32;
            #pragma unroll
            for (int nt = 0; nt < 4; nt++) {
                *(float2*)(rb + nt*8 + 2*tg)       = make_float2(e[nt][0], e[nt][1]);
                *(float2*)(rb + 8*S + nt*8 + 2*tg) = make_float2(e[nt][2], e[nt][3]);
            }
        }
        // pack P as fp16 2-limb A fragments
        uint32_t pah[2][4], pal[2][4];
        #pragma unroll
        for (int ks2 = 0; ks2 < 2; ks2++) {
            const int nA = 2*ks2, nB = 2*ks2 + 1;
            split_pack_h(e[nA][0], e[nA][1], pah[ks2][0], pal[ks2][0]);
            split_pack_h(e[nA][2], e[nA][3], pah[ks2][1], pal[ks2][1]);
            split_pack_h(e[nB][0], e[nB][1], pah[ks2][2], pal[ks2][2]);
            split_pack_h(e[nB][2], e[nB][3], pah[ks2][3], pal[ks2][3]);
        }

        if (kt + 1 < S/64) asm volatile("cp.async.wait_group 1;\n" ::: "memory");
        else               asm volatile("cp.async.wait_group 0;\n" ::: "memory");
        __syncthreads();

        // ctx += P @ Vh (one-sided 2-term fp16)
        #pragma unroll
        for (int ks2 = 0; ks2 < 2; ks2++) {
            const int kpb = wn*16 + ks2*8;
            #pragma unroll
            for (int nt = 0; nt < 8; nt++) {
                int nb = (nt*8 + g) * STRA + kpb + tg;
                uint32_t bhf[2] = { Vh[nb], Vh[nb+4] };
                mma_f16(cacc[nt], pah[ks2], bhf);
                mma_f16(cacc[nt], pal[ks2], bhf);
            }
        }
    }

    __syncthreads();
    float* xch = (float*)(sa + XCH_W);
    float* lp  = (float*)(sa + LP_W);
    if (tg == 0) {
        lp[wn*64 + wm*16 + g]     = lsum_g;
        lp[wn*64 + wm*16 + g + 8] = lsum_g8;
    }
    if (wn == 1) {
        #pragma unroll
        for (int nt = 0; nt < 8; nt++) {
            int r0 = (wm*16 + g)*64 + nt*8 + 2*tg;
            int r8 = (wm*16 + g + 8)*64 + nt*8 + 2*tg;
            xch[r0]     = cacc[nt][0];
            xch[r0 + 1] = cacc[nt][1];
            xch[r8]     = cacc[nt][2];
            xch[r8 + 1] = cacc[nt][3];
        }
    }
    __syncthreads();
    if (wn == 0) {
        float l0 = lp[wm*16 + g]     + lp[64 + wm*16 + g];
        float l8 = lp[wm*16 + g + 8] + lp[64 + wm*16 + g + 8];
        float inv0 = 1.0f / l0, inv8 = 1.0f / l8;
        int s0 = qt*64 + wm*16 + g;
        #pragma unroll
        for (int nt = 0; nt < 8; nt++) {
            int r0 = (wm*16 + g)*64 + nt*8 + 2*tg;
            int r8 = (wm*16 + g + 8)*64 + nt*8 + 2*tg;
            float v0 = (cacc[nt][0] + xch[r0])     * inv0;
            float v1 = (cacc[nt][1] + xch[r0 + 1]) * inv0;
            float v2 = (cacc[nt][2] + xch[r8])     * inv8;
            float v3 = (cacc[nt][3] + xch[r8 + 1]) * inv8;
            int pp = h*32 + nt*4 + tg;
            uint32_t hw, lw;
            split_pack_h(v0, v1, hw, lw);
            size_t p0 = ((size_t)b*S + s0) * KPAIRS + pp;
            ctxhi[p0] = hw; ctxlo[p0] = lw;
            split_pack_h(v2, v3, hw, lw);
            size_t p8 = ((size_t)b*S + s0 + 8) * KPAIRS + pp;
            ctxhi[p8] = hw; ctxlo[p8] = lw;
        }
    }
    if (write_attn && t < 64)
        gl[(size_t)bh*S + qt*64 + t] = lp[t] + lp[64 + t];
}

// -------------- normalize spilled exp-scores: pure 1/l scale -----------------
__global__ __launch_bounds__(256)
void norm_kernel(float* __restrict__ attn)
{
    const size_t i4 = (size_t)blockIdx.x * blockDim.x + threadIdx.x;
    if (i4 >= ATTN_ELEMS / 4) return;
    const size_t row = i4 >> 9;
    const float invl = 1.0f / g_l[row];
    float4 v = ((const float4*)attn)[i4];
    v.x *= invl;
    v.y *= invl;
    v.z *= invl;
    v.w *= invl;
    ((float4*)attn)[i4] = v;
}

// --------------------------------- launch ------------------------------------
extern "C" void kernel_launch(void* const* d_in, const int* in_sizes, int n_in,
                              void* d_out, int out_size)
{
    const float* query = (const float*)d_in[0];
    const float* key   = (const float*)d_in[1];
    const float* value = (const float*)d_in[2];
    const float* Wq = (const float*)d_in[3];
    const float* bq = (const float*)d_in[4];
    const float* Wk = (const float*)d_in[5];
    const float* bk = (const float*)d_in[6];
    const float* Wv = (const float*)d_in[7];
    const float* bv = (const float*)d_in[8];
    const float* Wo = (const float*)d_in[9];
    const float* bo = (const float*)d_in[10];

    float* out_ptr = (float*)d_out;
    const int write_attn = (out_size >= (int)(OUT_ELEMS + ATTN_ELEMS)) ? 1 : 0;
    float* attn_ptr = out_ptr + OUT_ELEMS;

    void* xqh; cudaGetSymbolAddress(&xqh, g_xq_hi);
    void* xql; cudaGetSymbolAddress(&xql, g_xq_lo);
    void* xkh; cudaGetSymbolAddress(&xkh, g_xk_hi);
    void* xkl; cudaGetSymbolAddress(&xkl, g_xk_lo);
    void* xvh; cudaGetSymbolAddress(&xvh, g_xv_hi);
    void* xvl; cudaGetSymbolAddress(&xvl, g_xv_lo);
    void* wqh; cudaGetSymbolAddress(&wqh, g_wq_h);
    void* wkh; cudaGetSymbolAddress(&wkh, g_wk_h);
    void* wvh; cudaGetSymbolAddress(&wvh, g_wv_h);
    void* woh; cudaGetSymbolAddress(&woh, g_wo_h);
    void* qh;  cudaGetSymbolAddress(&qh,  g_qhi);
    void* ql;  cudaGetSymbolAddress(&ql,  g_qlo);
    void* kh;  cudaGetSymbolAddress(&kh,  g_khi);
    void* kl;  cudaGetSymbolAddress(&kl,  g_klo);
    void* vth; cudaGetSymbolAddress(&vth, g_vth);
    void* ch;  cudaGetSymbolAddress(&ch,  g_chi);
    void* cl;  cudaGetSymbolAddress(&cl,  g_clo);
    void* ll;  cudaGetSymbolAddress(&ll,  g_l);

    const int npi = MROWS * KPAIRS;   // 2,097,152
    const int npw = E * KPAIRS;       // 524,288

    pack3_kernel<<<dim3(npi/256, 3), 256>>>(
        query, key, value,
        (uint32_t*)xqh, (uint32_t*)xql,
        (uint32_t*)xkh, (uint32_t*)xkl,
        (uint32_t*)xvh, (uint32_t*)xvl, npi);
    pack4h_kernel<<<dim3(npw/256, 4), 256>>>(
        Wq, Wk, Wv, Wo,
        (uint32_t*)wqh, (uint32_t*)wkh, (uint32_t*)wvh, (uint32_t*)woh, npw);

    cudaFuncSetAttribute(qkv_gemm, cudaFuncAttributeMaxDynamicSharedMemorySize, SMEM_G2);
    cudaFuncSetAttribute(gemm_out, cudaFuncAttributeMaxDynamicSharedMemorySize, SMEM_G2);
    cudaFuncSetAttribute(attn_tc,  cudaFuncAttributeMaxDynamicSharedMemorySize, SMEM_A4);

    dim3 gblk(256);

    qkv_gemm<<<dim3(16, 32, 3), gblk, SMEM_G2>>>(
        (const uint32_t*)xqh, (const uint32_t*)xql,
        (const uint32_t*)xkh, (const uint32_t*)xkl,
        (const uint32_t*)xvh, (const uint32_t*)xvl,
        (const uint32_t*)wqh, (const uint32_t*)wkh, (const uint32_t*)wvh,
        bq, bk, bv,
        (uint32_t*)qh, (uint32_t*)ql,
        (uint32_t*)kh, (uint32_t*)kl,
        (uint32_t*)vth);

    dim3 agrid(S/64, H, B);
    attn_tc<<<agrid, gblk, SMEM_A4>>>((const uint32_t*)qh, (const uint32_t*)ql,
                                      (const uint32_t*)kh, (const uint32_t*)kl,
                                      (const uint32_t*)vth,
                                      attn_ptr, (float*)ll,
                                      (uint32_t*)ch, (uint32_t*)cl, write_attn);

    if (write_attn) {
        const size_t n4 = ATTN_ELEMS / 4;
        norm_kernel<<<(unsigned)((n4 + 255) / 256), 256>>>(attn_ptr);
    }

    gemm_out<<<dim3(16, 32), gblk, SMEM_G2>>>(
        (const uint32_t*)ch, (const uint32_t*)cl,
        (const uint32_t*)woh,
        bo, out_ptr);
}

// round 17
// speedup vs baseline: 1.2679x; 1.0710x over previous
#include <cuda_runtime.h>
#include <cuda_bf16.h>
#include <cuda_fp16.h>
#include <stdint.h>
#include <math.h>

#define B 2
#define S 2048
#define E 1024
#define H 16
#define D 64
#define MROWS (B*S)                   // 4096
#define KPAIRS 512                    // 1024 floats -> 512 pairs
#define OUT_ELEMS (B*S*E)             // 4194304
#define ATTN_ELEMS ((size_t)B*H*S*S)  // 134217728

// ------------------------- device scratch (no runtime alloc) -----------------
__device__ uint32_t g_xq_hi[MROWS*KPAIRS], g_xq_lo[MROWS*KPAIRS];   // fp16 limbs
__device__ uint32_t g_xk_hi[MROWS*KPAIRS], g_xk_lo[MROWS*KPAIRS];
__device__ uint32_t g_xv_hi[MROWS*KPAIRS], g_xv_lo[MROWS*KPAIRS];
__device__ uint32_t g_wq_h[E*KPAIRS], g_wk_h[E*KPAIRS];             // fp16 single
__device__ uint32_t g_wv_h[E*KPAIRS], g_wo_h[E*KPAIRS];
__device__ uint32_t g_qhi[B*H*S*(D/2)], g_qlo[B*H*S*(D/2)];         // Q fp16 limbs
__device__ uint32_t g_kh[B*H*S*(D/2)];                              // K fp16 single
__device__ uint32_t g_vth[B*H*D*(S/2)];                             // V^T fp16 single
__device__ uint32_t g_chi[MROWS*KPAIRS], g_clo[MROWS*KPAIRS];       // ctx fp16 limbs
__device__ float    g_l[B*H*S];

// ------------------------------- helpers -------------------------------------
__device__ __forceinline__ void split_pack_h(float x0, float x1,   // fp16 limbs
                                             uint32_t& hi, uint32_t& lo) {
    __half h0 = __float2half(x0);
    __half h1 = __float2half(x1);
    __half l0 = __float2half(x0 - __half2float(h0));
    __half l1 = __float2half(x1 - __half2float(h1));
    hi = ((uint32_t)__half_as_ushort(h1) << 16) | __half_as_ushort(h0);
    lo = ((uint32_t)__half_as_ushort(l1) << 16) | __half_as_ushort(l0);
}

__device__ __forceinline__ uint32_t pack_h2(float x0, float x1) {  // fp16 pair
    return ((uint32_t)__half_as_ushort(__float2half(x1)) << 16)
         | __half_as_ushort(__float2half(x0));
}

__device__ __forceinline__ void mma_f16(float* d, const uint32_t* a, const uint32_t* b) {
    asm volatile(
        "mma.sync.aligned.m16n8k16.row.col.f32.f16.f16.f32 "
        "{%0,%1,%2,%3},{%4,%5,%6,%7},{%8,%9},{%0,%1,%2,%3};\n"
        : "+f"(d[0]), "+f"(d[1]), "+f"(d[2]), "+f"(d[3])
        : "r"(a[0]), "r"(a[1]), "r"(a[2]), "r"(a[3]), "r"(b[0]), "r"(b[1]));
}

__device__ __forceinline__ void cp16(uint32_t saddr, const void* gptr) {
    asm volatile("cp.async.cg.shared.global [%0], [%1], 16;\n"
                 :: "r"(saddr), "l"(gptr));
}
#define CP_COMMIT() asm volatile("cp.async.commit_group;\n" ::: "memory")

// ------------------- pack fp32 inputs -> fp16 hi/lo pairs --------------------
__global__ __launch_bounds__(256)
void pack3_kernel(const float* __restrict__ s0, const float* __restrict__ s1,
                  const float* __restrict__ s2,
                  uint32_t* __restrict__ h0, uint32_t* __restrict__ l0_,
                  uint32_t* __restrict__ h1, uint32_t* __restrict__ l1_,
                  uint32_t* __restrict__ h2, uint32_t* __restrict__ l2_,
                  int npairs)
{
    int i = blockIdx.x * 256 + threadIdx.x;
    if (i >= npairs) return;
    const float* src = (blockIdx.y == 0) ? s0 : (blockIdx.y == 1) ? s1 : s2;
    uint32_t* hi = (blockIdx.y == 0) ? h0 : (blockIdx.y == 1) ? h1 : h2;
    uint32_t* lo = (blockIdx.y == 0) ? l0_ : (blockIdx.y == 1) ? l1_ : l2_;
    float2 v = ((const float2*)src)[i];
    uint32_t h, l;
    split_pack_h(v.x, v.y, h, l);
    hi[i] = h; lo[i] = l;
}

// ------------------- pack fp32 weights -> single fp16 pairs ------------------
__global__ __launch_bounds__(256)
void pack4h_kernel(const float* __restrict__ s0, const float* __restrict__ s1,
                   const float* __restrict__ s2, const float* __restrict__ s3,
                   uint32_t* __restrict__ h0, uint32_t* __restrict__ h1,
                   uint32_t* __restrict__ h2, uint32_t* __restrict__ h3,
                   int npairs)
{
    int i = blockIdx.x * 256 + threadIdx.x;
    if (i >= npairs) return;
    const float* src = (blockIdx.y == 0) ? s0 : (blockIdx.y == 1) ? s1
                     : (blockIdx.y == 2) ? s2 : s3;
    uint32_t* hi = (blockIdx.y == 0) ? h0 : (blockIdx.y == 1) ? h1
                 : (blockIdx.y == 2) ? h2 : h3;
    float2 v = ((const float2*)src)[i];
    hi[i] = pack_h2(v.x, v.y);
}

// --------------------- GEMM core: one-sided 2-term fp16 ----------------------
#define STRG 36   // 32 pairs + pad
#define A2H_O 0
#define A2L_O (128*STRG)
#define W2H_O (256*STRG)
#define STAGE2_W (320*STRG)                // 11520 words/stage
#define SMEM_G2 (2*STAGE2_W*4)             // 92160 bytes

__device__ __forceinline__
void gemm_mainloop2(int rowBase, int colBase,
                    const uint32_t* __restrict__ Ahi, const uint32_t* __restrict__ Alo,
                    const uint32_t* __restrict__ Wh_,
                    uint32_t* sg, float acc[2][4][4])
{
    const uint32_t sbase = (uint32_t)__cvta_generic_to_shared(sg);
    const int t = threadIdx.x;

    auto issue = [&](int kt, int st) {
        const int kp0g = kt * 32;
        const uint32_t sb = sbase + (uint32_t)st * (STAGE2_W * 4);
        #pragma unroll
        for (int r = 0; r < 4; r++) {
            int idx = t + r * 256;
            int row = idx >> 3, c4 = (idx & 7) << 2;
            cp16(sb + (A2H_O + row*STRG + c4) * 4,
                 Ahi + (size_t)(rowBase + row) * KPAIRS + kp0g + c4);
            cp16(sb + (A2L_O + row*STRG + c4) * 4,
                 Alo + (size_t)(rowBase + row) * KPAIRS + kp0g + c4);
        }
        #pragma unroll
        for (int r = 0; r < 2; r++) {
            int idx = t + r * 256;
            int row = idx >> 3, c4 = (idx & 7) << 2;
            cp16(sb + (W2H_O + row*STRG + c4) * 4,
                 Wh_ + (size_t)(colBase + row) * KPAIRS + kp0g + c4);
        }
        CP_COMMIT();
    };

    const int lane = t & 31, g = lane >> 2, tg = lane & 3;
    const int warp = t >> 5, wm = warp >> 1, wn = warp & 1;

    issue(0, 0);
    issue(1, 1);

    for (int kt = 0; kt < 16; kt++) {
        if (kt < 15) asm volatile("cp.async.wait_group 1;\n" ::: "memory");
        else         asm volatile("cp.async.wait_group 0;\n" ::: "memory");
        __syncthreads();

        const uint32_t* Ah = sg + (kt & 1) * STAGE2_W + A2H_O;
        const uint32_t* Al = sg + (kt & 1) * STAGE2_W + A2L_O;
        const uint32_t* Wh = sg + (kt & 1) * STAGE2_W + W2H_O;

        #pragma unroll
        for (int ks = 0; ks < 4; ks++) {
            const int kp0 = ks * 8;
            uint32_t ah[2][4], al[2][4];
            #pragma unroll
            for (int mt = 0; mt < 2; mt++) {
                int r0 = (wm*32 + mt*16 + g) * STRG + kp0 + tg;
                int r8 = r0 + 8 * STRG;
                ah[mt][0] = Ah[r0]; ah[mt][1] = Ah[r8];
                ah[mt][2] = Ah[r0+4]; ah[mt][3] = Ah[r8+4];
                al[mt][0] = Al[r0]; al[mt][1] = Al[r8];
                al[mt][2] = Al[r0+4]; al[mt][3] = Al[r8+4];
            }
            #pragma unroll
            for (int nt = 0; nt < 4; nt++) {
                int nb = (wn*32 + nt*8 + g) * STRG + kp0 + tg;
                uint32_t bh[2] = { Wh[nb], Wh[nb+4] };
                #pragma unroll
                for (int mt = 0; mt < 2; mt++) {
                    mma_f16(acc[mt][nt], ah[mt], bh);
                    mma_f16(acc[mt][nt], al[mt], bh);
                }
            }
        }
        __syncthreads();
        if (kt + 2 < 16) issue(kt + 2, kt & 1);
    }
}

// ---------------- merged Q/K/V projection: grid.z selects operand ------------
// z=0: Q -> fp16 2-limb packed. z=1: K -> single fp16. z=2: V -> V^T fp16.
__global__ __launch_bounds__(256)
void qkv_gemm(const uint32_t* __restrict__ xqh, const uint32_t* __restrict__ xql,
              const uint32_t* __restrict__ xkh, const uint32_t* __restrict__ xkl,
              const uint32_t* __restrict__ xvh, const uint32_t* __restrict__ xvl,
              const uint32_t* __restrict__ wqh, const uint32_t* __restrict__ wkh,
              const uint32_t* __restrict__ wvh,
              const float* __restrict__ bq, const float* __restrict__ bk,
              const float* __restrict__ bv,
              uint32_t* __restrict__ qh, uint32_t* __restrict__ ql,
              uint32_t* __restrict__ kh,
              uint32_t* __restrict__ vth)
{
    extern __shared__ uint32_t sg[];
    const int z = blockIdx.z;
    const uint32_t* Ahi = (z == 0) ? xqh : (z == 1) ? xkh : xvh;
    const uint32_t* Alo = (z == 0) ? xql : (z == 1) ? xkl : xvl;
    const uint32_t* Wh_ = (z == 0) ? wqh : (z == 1) ? wkh : wvh;
    const float* bias   = (z == 0) ? bq  : (z == 1) ? bk  : bv;
    const float scale   = (z == 0) ? 0.125f : 1.0f;

    const int rowBase = blockIdx.y * 128, colBase = blockIdx.x * 64;
    float acc[2][4][4] = {};
    gemm_mainloop2(rowBase, colBase, Ahi, Alo, Wh_, sg, acc);

    const int t = threadIdx.x, lane = t & 31, g = lane >> 2, tg = lane & 3;
    const int warp = t >> 5, wm = warp >> 1, wn = warp & 1;

    #pragma unroll
    for (int mt = 0; mt < 2; mt++) {
        #pragma unroll
        for (int nt = 0; nt < 4; nt++) {
            int m0 = rowBase + wm*32 + mt*16 + g;
            int n  = colBase + wn*32 + nt*8 + 2*tg;
            float b0 = bias[n], b1 = bias[n+1];
            float v00 = (acc[mt][nt][0] + b0) * scale;
            float v01 = (acc[mt][nt][1] + b1) * scale;
            float v10 = (acc[mt][nt][2] + b0) * scale;
            float v11 = (acc[mt][nt][3] + b1) * scale;
            if (z == 0) {
                int hh = n >> 6, dp = (n >> 1) & 31;
                {
                    int bb = m0 >> 11, ss = m0 & 2047;
                    size_t p = ((size_t)(bb*H + hh)*S + ss) * (D/2) + dp;
                    uint32_t hw, lw; split_pack_h(v00, v01, hw, lw);
                    qh[p] = hw; ql[p] = lw;
                }
                {
                    int m8 = m0 + 8, bb = m8 >> 11, ss = m8 & 2047;
                    size_t p = ((size_t)(bb*H + hh)*S + ss) * (D/2) + dp;
                    uint32_t hw, lw; split_pack_h(v10, v11, hw, lw);
                    qh[p] = hw; ql[p] = lw;
                }
            } else if (z == 1) {
                int hh = n >> 6, dp = (n >> 1) & 31;
                {
                    int bb = m0 >> 11, ss = m0 & 2047;
                    size_t p = ((size_t)(bb*H + hh)*S + ss) * (D/2) + dp;
                    kh[p] = pack_h2(v00, v01);
                }
                {
                    int m8 = m0 + 8, bb = m8 >> 11, ss = m8 & 2047;
                    size_t p = ((size_t)(bb*H + hh)*S + ss) * (D/2) + dp;
                    kh[p] = pack_h2(v10, v11);
                }
            } else {
                float p00 = __shfl_down_sync(0xffffffffu, v00, 4);
                float p01 = __shfl_down_sync(0xffffffffu, v01, 4);
                float p10 = __shfl_down_sync(0xffffffffu, v10, 4);
                float p11 = __shfl_down_sync(0xffffffffu, v11, 4);
                if (!(g & 1)) {
                    int bb = m0 >> 11, ss = m0 & 2047;   // ss even
                    int hh = n >> 6, d0 = n & 63;
                    size_t base = ((size_t)(bb*H + hh) * D + d0) * (S/2) + (ss >> 1);
                    vth[base]             = pack_h2(v00, p00);
                    vth[base + (S/2)]     = pack_h2(v01, p01);
                    vth[base + 4]         = pack_h2(v10, p10);
                    vth[base + (S/2) + 4] = pack_h2(v11, p11);
                }
            }
        }
    }
}

// ---------------- out-projection GEMM (ctx fp16 limbs x Wo_h) ----------------
__global__ __launch_bounds__(256)
void gemm_out(const uint32_t* __restrict__ Ahi, const uint32_t* __restrict__ Alo,
              const uint32_t* __restrict__ Wh_,
              const float* __restrict__ bias,
              float* __restrict__ outf)
{
    extern __shared__ uint32_t sg[];
    const int rowBase = blockIdx.y * 128, colBase = blockIdx.x * 64;
    float acc[2][4][4] = {};
    gemm_mainloop2(rowBase, colBase, Ahi, Alo, Wh_, sg, acc);

    const int t = threadIdx.x, lane = t & 31, g = lane >> 2, tg = lane & 3;
    const int warp = t >> 5, wm = warp >> 1, wn = warp & 1;

    #pragma unroll
    for (int mt = 0; mt < 2; mt++) {
        #pragma unroll
        for (int nt = 0; nt < 4; nt++) {
            int m0 = rowBase + wm*32 + mt*16 + g;
            int n  = colBase + wn*32 + nt*8 + 2*tg;
            float b0 = bias[n], b1 = bias[n+1];
            *(float2*)(outf + (size_t)m0 * 1024 + n)
                = make_float2(acc[mt][nt][0] + b0, acc[mt][nt][1] + b1);
            *(float2*)(outf + (size_t)(m0 + 8) * 1024 + n)
                = make_float2(acc[mt][nt][2] + b0, acc[mt][nt][3] + b1);
        }
    }
}

// ------------------------------- attention -----------------------------------
// QK: one-sided 2-term fp16 (Q 2-limb x Kh). PV: same (P 2-limb x Vh).
// Register-resident P; max-free softmax; exp spilled from registers.
#define STRA 36
#define QH_W 0
#define QL_W 2304
#define KST_W 4608          // 2 stages of 2304 (Kh single limb)
#define VH_W 9216           // 2304 words
#define XCH_W KST_W         // epilogue exchange (64x64 fp32 = 4096 w) + lp 128
#define LP_W (KST_W + 4096)
#define SMEM_A5 (11520*4)   // 46080 bytes

__global__ __launch_bounds__(256)
void attn_tc(const uint32_t* __restrict__ qhi, const uint32_t* __restrict__ qlo,
             const uint32_t* __restrict__ kh,
             const uint32_t* __restrict__ vth,
             float* __restrict__ attn_raw,
             float* __restrict__ gl,
             uint32_t* __restrict__ ctxhi, uint32_t* __restrict__ ctxlo,
             int write_attn)
{
    extern __shared__ uint32_t sa[];
    const uint32_t sab = (uint32_t)__cvta_generic_to_shared(sa);
    uint32_t* Qh = sa + QH_W;
    uint32_t* Ql = sa + QL_W;
    uint32_t* Vh = sa + VH_W;

    const int qt = blockIdx.x, h = blockIdx.y, b = blockIdx.z;
    const int bh = b * H + h;
    const int t = threadIdx.x, lane = t & 31, g = lane >> 2, tg = lane & 3;
    const int warp = t >> 5, wm = warp >> 1, wn = warp & 1;

    {
        const size_t qb = ((size_t)bh * S + qt * 64) * (D/2);
        #pragma unroll
        for (int r = 0; r < 2; r++) {
            int idx = t + r * 256;
            int row = idx >> 3, c4 = (idx & 7) << 2;
            *(uint4*)&Qh[row*STRA + c4] = *(const uint4*)(qhi + qb + row*(D/2) + c4);
            *(uint4*)&Ql[row*STRA + c4] = *(const uint4*)(qlo + qb + row*(D/2) + c4);
        }
    }

    // prologue: prefetch K(0) into stage 0 (single limb: 512 chunks)
    {
        const size_t kb = ((size_t)bh * S) * (D/2);
        #pragma unroll
        for (int r = 0; r < 2; r++) {
            int idx = t + r * 256;
            int row = idx >> 3, c4 = (idx & 7) << 2;
            cp16(sab + (KST_W + row*STRA + c4)*4, kh + kb + row*(D/2) + c4);
        }
        CP_COMMIT();
    }

    float cacc[8][4] = {};
    float lsum_g = 0.0f, lsum_g8 = 0.0f;

    for (int kt = 0; kt < S/64; kt++) {
        __syncthreads();

        // issue V(kt)
        #pragma unroll
        for (int r = 0; r < 2; r++) {
            int idx = t + r * 256;
            int row = idx >> 3, c4 = (idx & 7) << 2;
            size_t vrow = ((size_t)bh * D + row) * (S/2) + kt*32;
            cp16(sab + (VH_W + row*STRA + c4)*4, vth + vrow + c4);
        }
        CP_COMMIT();
        // issue K(kt+1)
        if (kt + 1 < S/64) {
            const size_t kb = ((size_t)bh * S + (kt+1) * 64) * (D/2);
            const int st = (kt + 1) & 1;
            #pragma unroll
            for (int r = 0; r < 2; r++) {
                int idx = t + r * 256;
                int row = idx >> 3, c4 = (idx & 7) << 2;
                cp16(sab + (KST_W + st*2304 + row*STRA + c4)*4, kh + kb + row*(D/2) + c4);
            }
            CP_COMMIT();
        }

        // wait K(kt)
        if (kt + 1 < S/64) asm volatile("cp.async.wait_group 2;\n" ::: "memory");
        else               asm volatile("cp.async.wait_group 1;\n" ::: "memory");
        __syncthreads();

        const uint32_t* Khp = sa + KST_W + (kt & 1) * 2304;

        // S = Q @ K^T : one-sided 2-term fp16
        float sacc[4][4] = {};
        #pragma unroll
        for (int ks = 0; ks < 4; ks++) {
            const int kp0 = ks * 8;
            uint32_t ah[4], al[4];
            int r0 = (wm*16 + g) * STRA + kp0 + tg;
            int r8 = r0 + 8 * STRA;
            ah[0] = Qh[r0]; ah[1] = Qh[r8]; ah[2] = Qh[r0+4]; ah[3] = Qh[r8+4];
            al[0] = Ql[r0]; al[1] = Ql[r8]; al[2] = Ql[r0+4]; al[3] = Ql[r8+4];
            #pragma unroll
            for (int nt = 0; nt < 4; nt++) {
                int nb = (wn*32 + nt*8 + g) * STRA + kp0 + tg;
                uint32_t bhf[2] = { Khp[nb], Khp[nb+4] };
                mma_f16(sacc[nt], ah, bhf);
                mma_f16(sacc[nt], al, bhf);
            }
        }

        float e[4][4];
        #pragma unroll
        for (int nt = 0; nt < 4; nt++)
            #pragma unroll
            for (int i = 0; i < 4; i++)
                e[nt][i] = __expf(sacc[nt][i]);
        {
            float sg_ = 0.0f, s8_ = 0.0f;
            #pragma unroll
            for (int nt = 0; nt < 4; nt++) {
                sg_ += e[nt][0] + e[nt][1];
                s8_ += e[nt][2] + e[nt][3];
            }
            sg_ += __shfl_xor_sync(0xffffffffu, sg_, 1);
            sg_ += __shfl_xor_sync(0xffffffffu, sg_, 2);
            s8_ += __shfl_xor_sync(0xffffffffu, s8_, 1);
            s8_ += __shfl_xor_sync(0xffffffffu, s8_, 2);
            lsum_g  += sg_;
            lsum_g8 += s8_;
        }
        if (write_attn) {
            float* rb = attn_raw + (size_t)bh*S*S
                      + (size_t)(qt*64 + wm*16 + g) * S + kt*64 + wn*32;
            #pragma unroll
            for (int nt = 0; nt < 4; nt++) {
                *(float2*)(rb + nt*8 + 2*tg)       = make_float2(e[nt][0], e[nt][1]);
                *(float2*)(rb + 8*S + nt*8 + 2*tg) = make_float2(e[nt][2], e[nt][3]);
            }
        }
        uint32_t pah[2][4], pal[2][4];
        #pragma unroll
        for (int ks2 = 0; ks2 < 2; ks2++) {
            const int nA = 2*ks2, nB = 2*ks2 + 1;
            split_pack_h(e[nA][0], e[nA][1], pah[ks2][0], pal[ks2][0]);
            split_pack_h(e[nA][2], e[nA][3], pah[ks2][1], pal[ks2][1]);
            split_pack_h(e[nB][0], e[nB][1], pah[ks2][2], pal[ks2][2]);
            split_pack_h(e[nB][2], e[nB][3], pah[ks2][3], pal[ks2][3]);
        }

        // wait V(kt)
        if (kt + 1 < S/64) asm volatile("cp.async.wait_group 1;\n" ::: "memory");
        else               asm volatile("cp.async.wait_group 0;\n" ::: "memory");
        __syncthreads();

        // ctx += P @ Vh (one-sided 2-term fp16)
        #pragma unroll
        for (int ks2 = 0; ks2 < 2; ks2++) {
            const int kpb = wn*16 + ks2*8;
            #pragma unroll
            for (int nt = 0; nt < 8; nt++) {
                int nb = (nt*8 + g) * STRA + kpb + tg;
                uint32_t bhf[2] = { Vh[nb], Vh[nb+4] };
                mma_f16(cacc[nt], pah[ks2], bhf);
                mma_f16(cacc[nt], pal[ks2], bhf);
            }
        }
    }

    __syncthreads();
    float* xch = (float*)(sa + XCH_W);
    float* lp  = (float*)(sa + LP_W);
    if (tg == 0) {
        lp[wn*64 + wm*16 + g]     = lsum_g;
        lp[wn*64 + wm*16 + g + 8] = lsum_g8;
    }
    if (wn == 1) {
        #pragma unroll
        for (int nt = 0; nt < 8; nt++) {
            int r0 = (wm*16 + g)*64 + nt*8 + 2*tg;
            int r8 = (wm*16 + g + 8)*64 + nt*8 + 2*tg;
            xch[r0]     = cacc[nt][0];
            xch[r0 + 1] = cacc[nt][1];
            xch[r8]     = cacc[nt][2];
            xch[r8 + 1] = cacc[nt][3];
        }
    }
    __syncthreads();
    if (wn == 0) {
        float l0 = lp[wm*16 + g]     + lp[64 + wm*16 + g];
        float l8 = lp[wm*16 + g + 8] + lp[64 + wm*16 + g + 8];
        float inv0 = 1.0f / l0, inv8 = 1.0f / l8;
        int s0 = qt*64 + wm*16 + g;
        #pragma unroll
        for (int nt = 0; nt < 8; nt++) {
            int r0 = (wm*16 + g)*64 + nt*8 + 2*tg;
            int r8 = (wm*16 + g + 8)*64 + nt*8 + 2*tg;
            float v0 = (cacc[nt][0] + xch[r0])     * inv0;
            float v1 = (cacc[nt][1] + xch[r0 + 1]) * inv0;
            float v2 = (cacc[nt][2] + xch[r8])     * inv8;
            float v3 = (cacc[nt][3] + xch[r8 + 1]) * inv8;
            int pp = h*32 + nt*4 + tg;
            uint32_t hw, lw;
            split_pack_h(v0, v1, hw, lw);
            size_t p0 = ((size_t)b*S + s0) * KPAIRS + pp;
            ctxhi[p0] = hw; ctxlo[p0] = lw;
            split_pack_h(v2, v3, hw, lw);
            size_t p8 = ((size_t)b*S + s0 + 8) * KPAIRS + pp;
            ctxhi[p8] = hw; ctxlo[p8] = lw;
        }
    }
    if (write_attn && t < 64)
        gl[(size_t)bh*S + qt*64 + t] = lp[t] + lp[64 + t];
}

// -------------- normalize spilled exp-scores: pure 1/l scale -----------------
__global__ __launch_bounds__(256)
void norm_kernel(float* __restrict__ attn)
{
    const size_t i4 = (size_t)blockIdx.x * blockDim.x + threadIdx.x;
    if (i4 >= ATTN_ELEMS / 4) return;
    const size_t row = i4 >> 9;
    const float invl = 1.0f / g_l[row];
    float4 v = ((const float4*)attn)[i4];
    v.x *= invl;
    v.y *= invl;
    v.z *= invl;
    v.w *= invl;
    ((float4*)attn)[i4] = v;
}

// --------------------------------- launch ------------------------------------
extern "C" void kernel_launch(void* const* d_in, const int* in_sizes, int n_in,
                              void* d_out, int out_size)
{
    const float* query = (const float*)d_in[0];
    const float* key   = (const float*)d_in[1];
    const float* value = (const float*)d_in[2];
    const float* Wq = (const float*)d_in[3];
    const float* bq = (const float*)d_in[4];
    const float* Wk = (const float*)d_in[5];
    const float* bk = (const float*)d_in[6];
    const float* Wv = (const float*)d_in[7];
    const float* bv = (const float*)d_in[8];
    const float* Wo = (const float*)d_in[9];
    const float* bo = (const float*)d_in[10];

    float* out_ptr = (float*)d_out;
    const int write_attn = (out_size >= (int)(OUT_ELEMS + ATTN_ELEMS)) ? 1 : 0;
    float* attn_ptr = out_ptr + OUT_ELEMS;

    void* xqh; cudaGetSymbolAddress(&xqh, g_xq_hi);
    void* xql; cudaGetSymbolAddress(&xql, g_xq_lo);
    void* xkh; cudaGetSymbolAddress(&xkh, g_xk_hi);
    void* xkl; cudaGetSymbolAddress(&xkl, g_xk_lo);
    void* xvh; cudaGetSymbolAddress(&xvh, g_xv_hi);
    void* xvl; cudaGetSymbolAddress(&xvl, g_xv_lo);
    void* wqh; cudaGetSymbolAddress(&wqh, g_wq_h);
    void* wkh; cudaGetSymbolAddress(&wkh, g_wk_h);
    void* wvh; cudaGetSymbolAddress(&wvh, g_wv_h);
    void* woh; cudaGetSymbolAddress(&woh, g_wo_h);
    void* qh;  cudaGetSymbolAddress(&qh,  g_qhi);
    void* ql;  cudaGetSymbolAddress(&ql,  g_qlo);
    void* kh;  cudaGetSymbolAddress(&kh,  g_kh);
    void* vth; cudaGetSymbolAddress(&vth, g_vth);
    void* ch;  cudaGetSymbolAddress(&ch,  g_chi);
    void* cl;  cudaGetSymbolAddress(&cl,  g_clo);
    void* ll;  cudaGetSymbolAddress(&ll,  g_l);

    const int npi = MROWS * KPAIRS;   // 2,097,152
    const int npw = E * KPAIRS;       // 524,288

    pack3_kernel<<<dim3(npi/256, 3), 256>>>(
        query, key, value,
        (uint32_t*)xqh, (uint32_t*)xql,
        (uint32_t*)xkh, (uint32_t*)xkl,
        (uint32_t*)xvh, (uint32_t*)xvl, npi);
    pack4h_kernel<<<dim3(npw/256, 4), 256>>>(
        Wq, Wk, Wv, Wo,
        (uint32_t*)wqh, (uint32_t*)wkh, (uint32_t*)wvh, (uint32_t*)woh, npw);

    cudaFuncSetAttribute(qkv_gemm, cudaFuncAttributeMaxDynamicSharedMemorySize, SMEM_G2);
    cudaFuncSetAttribute(gemm_out, cudaFuncAttributeMaxDynamicSharedMemorySize, SMEM_G2);
    cudaFuncSetAttribute(attn_tc,  cudaFuncAttributeMaxDynamicSharedMemorySize, SMEM_A5);

    dim3 gblk(256);

    qkv_gemm<<<dim3(16, 32, 3), gblk, SMEM_G2>>>(
        (const uint32_t*)xqh, (const uint32_t*)xql,
        (const uint32_t*)xkh, (const uint32_t*)xkl,
        (const uint32_t*)xvh, (const uint32_t*)xvl,
        (const uint32_t*)wqh, (const uint32_t*)wkh, (const uint32_t*)wvh,
        bq, bk, bv,
        (uint32_t*)qh, (uint32_t*)ql,
        (uint32_t*)kh,
        (uint32_t*)vth);

    dim3 agrid(S/64, H, B);
    attn_tc<<<agrid, gblk, SMEM_A5>>>((const uint32_t*)qh, (const uint32_t*)ql,
                                      (const uint32_t*)kh,
                                      (const uint32_t*)vth,
                                      attn_ptr, (float*)ll,
                                      (uint32_t*)ch, (uint32_t*)cl, write_attn);

    if (write_attn) {
        const size_t n4 = ATTN_ELEMS / 4;
        norm_kernel<<<(unsigned)((n4 + 255) / 256), 256>>>(attn_ptr);
    }

    gemm_out<<<dim3(16, 32), gblk, SMEM_G2>>>(
        (const uint32_t*)ch, (const uint32_t*)cl,
        (const uint32_t*)woh,
        bo, out_ptr);
}